// round 1
// baseline (speedup 1.0000x reference)
#include <cuda_runtime.h>

#define M_TOK 16384   // B*S = 4*4096
#define E_DIM 1024
#define NQ    64

// ---- scratch (allocation-free rule: __device__ globals) ----
__device__ float g_z[(size_t)M_TOK * E_DIM];     // z, 64MB
__device__ float g_attn[(size_t)M_TOK * E_DIM];  // attn_out, then reused for ffn_out
__device__ float g_x1[(size_t)M_TOK * E_DIM];    // x1, 64MB
__device__ float g_q[(size_t)M_TOK * NQ];        // q, 4MB

// ============================================================
// Kernel 1: z = cos(x + a0[d]) * cos(a1[d]),  d = e % 64
// ============================================================
__global__ __launch_bounds__(256) void z_kernel(const float* __restrict__ x,
                                                const float* __restrict__ aqp,
                                                float* __restrict__ z) {
    __shared__ float sa0[NQ], sc1[NQ];
    if (threadIdx.x < NQ) {
        sa0[threadIdx.x] = aqp[threadIdx.x * 3 + 0];
        sc1[threadIdx.x] = __cosf(aqp[threadIdx.x * 3 + 1]);
    }
    __syncthreads();
    int i = blockIdx.x * blockDim.x + threadIdx.x;   // float4 index
    int d = (i * 4) & 63;                            // 64 % 4 == 0 -> no wrap inside a float4
    float4 v = ((const float4*)x)[i];
    float4 o;
    o.x = __cosf(v.x + sa0[d + 0]) * sc1[d + 0];
    o.y = __cosf(v.y + sa0[d + 1]) * sc1[d + 1];
    o.z = __cosf(v.z + sa0[d + 2]) * sc1[d + 2];
    o.w = __cosf(v.w + sa0[d + 3]) * sc1[d + 3];
    ((float4*)z)[i] = o;
}

// ============================================================
// GEMM (TN): C[m][n] = sum_k A[m][k] * B[n][k] + bias[n]
// A: [M_TOK, K] row-major, B: [1024, K] row-major, C: [M_TOK, 1024]
// 128x128 tile, BK=16, 256 threads, 8x8 per thread.
// ============================================================
#define BM 128
#define BN 128
#define BK 16

__global__ __launch_bounds__(256) void gemm_tn(const float* __restrict__ A,
                                               const float* __restrict__ B,
                                               const float* __restrict__ bias,
                                               float* __restrict__ C,
                                               int K) {
    __shared__ float As[BK][BM + 4];   // +4 floats keeps 16B alignment, kills STS conflicts
    __shared__ float Bs[BK][BN + 4];
    const int tid = threadIdx.x;
    const int tx = tid & 15;
    const int ty = tid >> 4;
    const int m0 = blockIdx.y * BM;
    const int n0 = blockIdx.x * BN;

    float acc[8][8] = {};

    for (int k0 = 0; k0 < K; k0 += BK) {
        // load A and B tiles (transposed into smem), 2 float4 each per thread
        #pragma unroll
        for (int l = 0; l < 2; ++l) {
            int f  = tid + l * 256;        // float4 id 0..511
            int r  = f >> 2;               // tile row 0..127
            int kq = (f & 3) << 2;         // k offset 0,4,8,12
            float4 va = *(const float4*)&A[(size_t)(m0 + r) * K + k0 + kq];
            As[kq + 0][r] = va.x; As[kq + 1][r] = va.y;
            As[kq + 2][r] = va.z; As[kq + 3][r] = va.w;
            float4 vb = *(const float4*)&B[(size_t)(n0 + r) * K + k0 + kq];
            Bs[kq + 0][r] = vb.x; Bs[kq + 1][r] = vb.y;
            Bs[kq + 2][r] = vb.z; Bs[kq + 3][r] = vb.w;
        }
        __syncthreads();

        #pragma unroll
        for (int kk = 0; kk < BK; ++kk) {
            float ra[8], rb[8];
            *(float4*)(ra)     = *(const float4*)&As[kk][ty * 8];
            *(float4*)(ra + 4) = *(const float4*)&As[kk][ty * 8 + 4];
            *(float4*)(rb)     = *(const float4*)&Bs[kk][tx * 8];
            *(float4*)(rb + 4) = *(const float4*)&Bs[kk][tx * 8 + 4];
            #pragma unroll
            for (int i = 0; i < 8; ++i)
                #pragma unroll
                for (int j = 0; j < 8; ++j)
                    acc[i][j] = fmaf(ra[i], rb[j], acc[i][j]);
        }
        __syncthreads();
    }

    float4 bv0 = *(const float4*)&bias[n0 + tx * 8];
    float4 bv1 = *(const float4*)&bias[n0 + tx * 8 + 4];
    #pragma unroll
    for (int i = 0; i < 8; ++i) {
        float* crow = &C[(size_t)(m0 + ty * 8 + i) * E_DIM + n0 + tx * 8];
        float4 o0 = {acc[i][0] + bv0.x, acc[i][1] + bv0.y, acc[i][2] + bv0.z, acc[i][3] + bv0.w};
        float4 o1 = {acc[i][4] + bv1.x, acc[i][5] + bv1.y, acc[i][6] + bv1.z, acc[i][7] + bv1.w};
        *(float4*)(crow)     = o0;
        *(float4*)(crow + 4) = o1;
    }
}

// ============================================================
// Kernel 3: x1 = LN(x + attn)*w+b ; q = cos(x1[:, :64]+f0)*cos(f1)
// warp per row (32 elems/lane), 8 rows per CTA
// ============================================================
__global__ __launch_bounds__(256) void ln1_kernel(const float* __restrict__ x,
                                                  const float* __restrict__ attn,
                                                  const float* __restrict__ w,
                                                  const float* __restrict__ b,
                                                  const float* __restrict__ fqp,
                                                  float* __restrict__ x1,
                                                  float* __restrict__ q) {
    int row  = blockIdx.x * 8 + (threadIdx.x >> 5);
    int lane = threadIdx.x & 31;
    const float4* px = (const float4*)(x    + (size_t)row * E_DIM);
    const float4* pa = (const float4*)(attn + (size_t)row * E_DIM);
    float4 v[8];
    float s = 0.f, ss = 0.f;
    #pragma unroll
    for (int j = 0; j < 8; ++j) {
        float4 a = px[lane + j * 32];
        float4 t = pa[lane + j * 32];
        float4 u = {a.x + t.x, a.y + t.y, a.z + t.z, a.w + t.w};
        v[j] = u;
        s  += u.x + u.y + u.z + u.w;
        ss += u.x * u.x + u.y * u.y + u.z * u.z + u.w * u.w;
    }
    #pragma unroll
    for (int o = 16; o; o >>= 1) {
        s  += __shfl_xor_sync(0xffffffffu, s, o);
        ss += __shfl_xor_sync(0xffffffffu, ss, o);
    }
    float mu  = s * (1.f / E_DIM);
    float var = ss * (1.f / E_DIM) - mu * mu;
    float rs  = rsqrtf(var + 1e-5f);

    float4* po = (float4*)(x1 + (size_t)row * E_DIM);
    #pragma unroll
    for (int j = 0; j < 8; ++j) {
        int c4 = lane + j * 32;
        float4 wv = ((const float4*)w)[c4];
        float4 bv = ((const float4*)b)[c4];
        float4 u  = v[j];
        float4 o;
        o.x = (u.x - mu) * rs * wv.x + bv.x;
        o.y = (u.y - mu) * rs * wv.y + bv.y;
        o.z = (u.z - mu) * rs * wv.z + bv.z;
        o.w = (u.w - mu) * rs * wv.w + bv.w;
        po[c4] = o;
        if (j == 0 && lane < 16) {   // first 64 cols -> q
            int k = lane * 4;
            float4 qo;
            qo.x = __cosf(o.x + fqp[(k + 0) * 3]) * __cosf(fqp[(k + 0) * 3 + 1]);
            qo.y = __cosf(o.y + fqp[(k + 1) * 3]) * __cosf(fqp[(k + 1) * 3 + 1]);
            qo.z = __cosf(o.z + fqp[(k + 2) * 3]) * __cosf(fqp[(k + 2) * 3 + 1]);
            qo.w = __cosf(o.w + fqp[(k + 3) * 3]) * __cosf(fqp[(k + 3) * 3 + 1]);
            *(float4*)(q + (size_t)row * NQ + k) = qo;
        }
    }
}

// ============================================================
// Kernel 5: out = LN(x1 + ffn)*w+b
// ============================================================
__global__ __launch_bounds__(256) void ln2_kernel(const float* __restrict__ x1,
                                                  const float* __restrict__ ffn,
                                                  const float* __restrict__ w,
                                                  const float* __restrict__ b,
                                                  float* __restrict__ out) {
    int row  = blockIdx.x * 8 + (threadIdx.x >> 5);
    int lane = threadIdx.x & 31;
    const float4* px = (const float4*)(x1  + (size_t)row * E_DIM);
    const float4* pf = (const float4*)(ffn + (size_t)row * E_DIM);
    float4 v[8];
    float s = 0.f, ss = 0.f;
    #pragma unroll
    for (int j = 0; j < 8; ++j) {
        float4 a = px[lane + j * 32];
        float4 t = pf[lane + j * 32];
        float4 u = {a.x + t.x, a.y + t.y, a.z + t.z, a.w + t.w};
        v[j] = u;
        s  += u.x + u.y + u.z + u.w;
        ss += u.x * u.x + u.y * u.y + u.z * u.z + u.w * u.w;
    }
    #pragma unroll
    for (int o = 16; o; o >>= 1) {
        s  += __shfl_xor_sync(0xffffffffu, s, o);
        ss += __shfl_xor_sync(0xffffffffu, ss, o);
    }
    float mu  = s * (1.f / E_DIM);
    float var = ss * (1.f / E_DIM) - mu * mu;
    float rs  = rsqrtf(var + 1e-5f);

    float4* po = (float4*)(out + (size_t)row * E_DIM);
    #pragma unroll
    for (int j = 0; j < 8; ++j) {
        int c4 = lane + j * 32;
        float4 wv = ((const float4*)w)[c4];
        float4 bv = ((const float4*)b)[c4];
        float4 u  = v[j];
        float4 o;
        o.x = (u.x - mu) * rs * wv.x + bv.x;
        o.y = (u.y - mu) * rs * wv.y + bv.y;
        o.z = (u.z - mu) * rs * wv.z + bv.z;
        o.w = (u.w - mu) * rs * wv.w + bv.w;
        po[c4] = o;
    }
}

// ============================================================
// launcher
// ============================================================
extern "C" void kernel_launch(void* const* d_in, const int* in_sizes, int n_in,
                              void* d_out, int out_size) {
    const float* x   = (const float*)d_in[0];
    const float* aqp = (const float*)d_in[1];   // attn_q_params (64,3)
    const float* opw = (const float*)d_in[2];   // out_proj_w (1024,1024)
    const float* opb = (const float*)d_in[3];   // out_proj_b (1024)
    const float* fqp = (const float*)d_in[4];   // ffn_q_params (64,3)
    const float* flw = (const float*)d_in[5];   // ffn_lin_w (1024,64)
    const float* flb = (const float*)d_in[6];   // ffn_lin_b (1024)
    const float* n1w = (const float*)d_in[7];
    const float* n1b = (const float*)d_in[8];
    const float* n2w = (const float*)d_in[9];
    const float* n2b = (const float*)d_in[10];
    float* out = (float*)d_out;

    float *z, *attn, *x1, *q;
    cudaGetSymbolAddress((void**)&z,    g_z);
    cudaGetSymbolAddress((void**)&attn, g_attn);
    cudaGetSymbolAddress((void**)&x1,   g_x1);
    cudaGetSymbolAddress((void**)&q,    g_q);

    // 1) z
    z_kernel<<<(M_TOK * E_DIM / 4) / 256, 256>>>(x, aqp, z);
    // 2) attn = z @ out_proj_w^T + b
    dim3 g1(E_DIM / BN, M_TOK / BM);
    gemm_tn<<<g1, 256>>>(z, opw, opb, attn, E_DIM);
    // 3) x1 = LN1(x + attn); q = cos(x1[:, :64]+f0)*cos(f1)
    ln1_kernel<<<M_TOK / 8, 256>>>(x, attn, n1w, n1b, fqp, x1, q);
    // 4) ffn = q @ ffn_lin_w^T + b  (reuse attn buffer, K = 64)
    gemm_tn<<<g1, 256>>>(q, flw, flb, attn, NQ);
    // 5) out = LN2(x1 + ffn)
    ln2_kernel<<<M_TOK / 8, 256>>>(x1, attn, n2w, n2b, out);
}

// round 3
// speedup vs baseline: 2.2802x; 2.2802x over previous
#include <cuda_runtime.h>
#include <cuda_bf16.h>
#include <cstdint>

#define M_TOK 16384   // B*S
#define E_DIM 1024
#define NQ    64

// ---------------- scratch (__device__ globals; no allocs) ----------------
__device__ float         g_attn[(size_t)M_TOK * E_DIM];
__device__ float         g_x1[(size_t)M_TOK * E_DIM];
__device__ __nv_bfloat16 g_zhi[(size_t)M_TOK * E_DIM];
__device__ __nv_bfloat16 g_zlo[(size_t)M_TOK * E_DIM];
__device__ __nv_bfloat16 g_whi[(size_t)E_DIM * E_DIM];
__device__ __nv_bfloat16 g_wlo[(size_t)E_DIM * E_DIM];
__device__ __nv_bfloat16 g_w2hi[(size_t)E_DIM * NQ];
__device__ __nv_bfloat16 g_w2lo[(size_t)E_DIM * NQ];
__device__ __nv_bfloat16 g_qhi[(size_t)M_TOK * NQ];
__device__ __nv_bfloat16 g_qlo[(size_t)M_TOK * NQ];

// ---------------- PTX helpers (compute_100-safe: no tcgen05/TMA) ---------
__device__ __forceinline__ uint32_t smem_u32(const void* p) {
    uint32_t a;
    asm("{ .reg .u64 t; cvta.to.shared.u64 t, %1; cvt.u32.u64 %0, t; }" : "=r"(a) : "l"(p));
    return a;
}
__device__ __forceinline__ void cp16(uint32_t dst, const void* src) {
    asm volatile("cp.async.cg.shared.global [%0], [%1], 16;" :: "r"(dst), "l"(src));
}
#define CP_COMMIT() asm volatile("cp.async.commit_group;" ::: "memory")
#define CP_WAIT1()  asm volatile("cp.async.wait_group 1;" ::: "memory")
#define CP_WAIT0()  asm volatile("cp.async.wait_group 0;" ::: "memory")

#define LDSM4(r, addr)                                                        \
    asm volatile("ldmatrix.sync.aligned.m8n8.x4.shared.b16 {%0,%1,%2,%3}, [%4];" \
        : "=r"((r)[0]), "=r"((r)[1]), "=r"((r)[2]), "=r"((r)[3]) : "r"(addr))

#define MMA16816(d, a, b)                                                     \
    asm volatile("mma.sync.aligned.m16n8k16.row.col.f32.bf16.bf16.f32 "       \
        "{%0,%1,%2,%3}, {%4,%5,%6,%7}, {%8,%9}, {%0,%1,%2,%3};"               \
        : "+f"((d)[0]), "+f"((d)[1]), "+f"((d)[2]), "+f"((d)[3])              \
        : "r"((a)[0]), "r"((a)[1]), "r"((a)[2]), "r"((a)[3]),                 \
          "r"((b)[0]), "r"((b)[1]))

// ---------------- bf16-split GEMM: C = A*B^T + bias ----------------------
// A = Ahi+Alo [M,K] row-major bf16; B = Bhi+Blo [N,K] row-major bf16.
// C ~= Ah*Bh + Ah*Bl + Al*Bh  (fp32 accum).  CTA 128x128, BK=32.
#define BM 128
#define BN 128
#define BK 32
#define ROWB 80                      // smem row stride bytes (64 data + 16 pad)
#define MAT_B (128 * ROWB)           // 10240 bytes per 128x32 bf16 tile
#define STG   (4 * MAT_B)            // Ah, Al, Bh, Bl
#define SM_BIAS (2 * STG)            // bias floats after the two stages
#define SM_TOT  (SM_BIAS + BN * 4)

__global__ __launch_bounds__(256) void mma_gemm(
    const __nv_bfloat16* __restrict__ Ahi, const __nv_bfloat16* __restrict__ Alo,
    const __nv_bfloat16* __restrict__ Bhi, const __nv_bfloat16* __restrict__ Blo,
    const float* __restrict__ bias, float* __restrict__ Cout, int K) {
    extern __shared__ char smem[];
    const uint32_t sbase = smem_u32(smem);
    float* sbias = (float*)(smem + SM_BIAS);
    const int tid = threadIdx.x, wid = tid >> 5, lane = tid & 31;
    const int m0 = blockIdx.y * BM, n0 = blockIdx.x * BN;
    const int m_off = (wid & 1) * 64;        // warp tile 64x32, warps 2x4
    const int n_off = (wid >> 1) * 32;

    if (tid < BN) sbias[tid] = bias[n0 + tid];

    // per-thread ldmatrix base byte offsets (within one matrix tile)
    const uint32_t aRow = (uint32_t)(m_off + (lane & 15)) * ROWB + (lane >> 4) * 16;
    const uint32_t bRow = (uint32_t)(n_off + ((lane >> 4) << 3) + (lane & 7)) * ROWB
                        + ((lane >> 3) & 1) * 16;

    float acc[4][4][4] = {};   // [mi][ni][4]

    auto load_stage = [&](int s, int kc0) {
        uint32_t sb = sbase + s * STG;
        #pragma unroll
        for (int i = 0; i < 2; ++i) {
            int c = tid + i * 256;               // 512 16B-chunks per matrix
            int r = c >> 2, ch = c & 3;
            uint32_t d = (uint32_t)r * ROWB + ch * 16;
            size_t goA = (size_t)(m0 + r) * K + kc0 + ch * 8;
            size_t goB = (size_t)(n0 + r) * K + kc0 + ch * 8;
            cp16(sb + d,             Ahi + goA);
            cp16(sb + MAT_B + d,     Alo + goA);
            cp16(sb + 2 * MAT_B + d, Bhi + goB);
            cp16(sb + 3 * MAT_B + d, Blo + goB);
        }
        CP_COMMIT();
    };

    const int C = K / BK;
    load_stage(0, 0);

    for (int ki = 0; ki < C; ++ki) {
        int cur = ki & 1;
        if (ki + 1 < C) { load_stage(cur ^ 1, (ki + 1) * BK); CP_WAIT1(); }
        else           { CP_WAIT0(); }
        __syncthreads();

        uint32_t base = sbase + cur * STG;
        uint32_t aH = base + aRow;
        uint32_t aL = aH + MAT_B;
        uint32_t bH = base + 2 * MAT_B + bRow;
        uint32_t bL = bH + MAT_B;

        #pragma unroll
        for (int ks = 0; ks < 2; ++ks) {         // two k16 steps per BK=32
            uint32_t ah[4][4], al[4][4], bh[4][2], bl[4][2];
            #pragma unroll
            for (int mi = 0; mi < 4; ++mi) {
                LDSM4(ah[mi], aH + ks * 32 + mi * 16 * ROWB);
                LDSM4(al[mi], aL + ks * 32 + mi * 16 * ROWB);
            }
            #pragma unroll
            for (int p = 0; p < 2; ++p) {        // each x4 covers two n8 groups
                uint32_t t[4];
                LDSM4(t, bH + ks * 32 + p * 16 * ROWB);
                bh[2 * p][0] = t[0]; bh[2 * p][1] = t[1];
                bh[2 * p + 1][0] = t[2]; bh[2 * p + 1][1] = t[3];
                LDSM4(t, bL + ks * 32 + p * 16 * ROWB);
                bl[2 * p][0] = t[0]; bl[2 * p][1] = t[1];
                bl[2 * p + 1][0] = t[2]; bl[2 * p + 1][1] = t[3];
            }
            #pragma unroll
            for (int mi = 0; mi < 4; ++mi)
                #pragma unroll
                for (int ni = 0; ni < 4; ++ni) {
                    MMA16816(acc[mi][ni], ah[mi], bh[ni]);
                    MMA16816(acc[mi][ni], ah[mi], bl[ni]);
                    MMA16816(acc[mi][ni], al[mi], bh[ni]);
                }
        }
        __syncthreads();
    }

    // epilogue: c0,c1 -> (m, n..n+1); c2,c3 -> (m+8, n..n+1)
    #pragma unroll
    for (int mi = 0; mi < 4; ++mi) {
        int m = m0 + m_off + mi * 16 + (lane >> 2);
        #pragma unroll
        for (int ni = 0; ni < 4; ++ni) {
            int nl = n_off + ni * 8 + 2 * (lane & 3);
            float2 bv = *(float2*)&sbias[nl];
            float* p0 = Cout + (size_t)m * E_DIM + n0 + nl;
            float* p1 = p0 + 8 * E_DIM;
            float2 o0 = {acc[mi][ni][0] + bv.x, acc[mi][ni][1] + bv.y};
            float2 o1 = {acc[mi][ni][2] + bv.x, acc[mi][ni][3] + bv.y};
            *(float2*)p0 = o0;
            *(float2*)p1 = o1;
        }
    }
}

// ---------------- z = cos(x + a0[e%64])*cos(a1[e%64]), split to bf16 -----
union BPack { __nv_bfloat16 b[4]; uint2 u; };

__global__ __launch_bounds__(256) void z_split_kernel(const float* __restrict__ x,
                                                      const float* __restrict__ aqp,
                                                      __nv_bfloat16* __restrict__ zhi,
                                                      __nv_bfloat16* __restrict__ zlo) {
    __shared__ float sa0[NQ], sc1[NQ];
    if (threadIdx.x < NQ) {
        sa0[threadIdx.x] = aqp[threadIdx.x * 3 + 0];
        sc1[threadIdx.x] = __cosf(aqp[threadIdx.x * 3 + 1]);
    }
    __syncthreads();
    int i = blockIdx.x * blockDim.x + threadIdx.x;
    int d = (i * 4) & 63;
    float4 v = ((const float4*)x)[i];
    float z0 = __cosf(v.x + sa0[d + 0]) * sc1[d + 0];
    float z1 = __cosf(v.y + sa0[d + 1]) * sc1[d + 1];
    float z2 = __cosf(v.z + sa0[d + 2]) * sc1[d + 2];
    float z3 = __cosf(v.w + sa0[d + 3]) * sc1[d + 3];
    BPack h, l;
    h.b[0] = __float2bfloat16(z0); l.b[0] = __float2bfloat16(z0 - __bfloat162float(h.b[0]));
    h.b[1] = __float2bfloat16(z1); l.b[1] = __float2bfloat16(z1 - __bfloat162float(h.b[1]));
    h.b[2] = __float2bfloat16(z2); l.b[2] = __float2bfloat16(z2 - __bfloat162float(h.b[2]));
    h.b[3] = __float2bfloat16(z3); l.b[3] = __float2bfloat16(z3 - __bfloat162float(h.b[3]));
    ((uint2*)zhi)[i] = h.u;
    ((uint2*)zlo)[i] = l.u;
}

// ---------------- weight split ----------------
__global__ __launch_bounds__(256) void w_split_kernel(const float* __restrict__ w,
                                                      __nv_bfloat16* __restrict__ hi,
                                                      __nv_bfloat16* __restrict__ lo, int n) {
    for (int i = blockIdx.x * blockDim.x + threadIdx.x; i < n; i += gridDim.x * blockDim.x) {
        float v = w[i];
        __nv_bfloat16 h = __float2bfloat16(v);
        hi[i] = h;
        lo[i] = __float2bfloat16(v - __bfloat162float(h));
    }
}

// ---------------- LN1 + q split ----------------
__global__ __launch_bounds__(256) void ln1_kernel(const float* __restrict__ x,
                                                  const float* __restrict__ attn,
                                                  const float* __restrict__ w,
                                                  const float* __restrict__ b,
                                                  const float* __restrict__ fqp,
                                                  float* __restrict__ x1,
                                                  __nv_bfloat16* __restrict__ qhi,
                                                  __nv_bfloat16* __restrict__ qlo) {
    int row  = blockIdx.x * 8 + (threadIdx.x >> 5);
    int lane = threadIdx.x & 31;
    const float4* px = (const float4*)(x    + (size_t)row * E_DIM);
    const float4* pa = (const float4*)(attn + (size_t)row * E_DIM);
    float4 v[8];
    float s = 0.f, ss = 0.f;
    #pragma unroll
    for (int j = 0; j < 8; ++j) {
        float4 a = px[lane + j * 32];
        float4 t = pa[lane + j * 32];
        float4 u = {a.x + t.x, a.y + t.y, a.z + t.z, a.w + t.w};
        v[j] = u;
        s  += u.x + u.y + u.z + u.w;
        ss += u.x * u.x + u.y * u.y + u.z * u.z + u.w * u.w;
    }
    #pragma unroll
    for (int o = 16; o; o >>= 1) {
        s  += __shfl_xor_sync(0xffffffffu, s, o);
        ss += __shfl_xor_sync(0xffffffffu, ss, o);
    }
    float mu  = s * (1.f / E_DIM);
    float var = ss * (1.f / E_DIM) - mu * mu;
    float rs  = rsqrtf(var + 1e-5f);

    float4* po = (float4*)(x1 + (size_t)row * E_DIM);
    #pragma unroll
    for (int j = 0; j < 8; ++j) {
        int c4 = lane + j * 32;
        float4 wv = ((const float4*)w)[c4];
        float4 bv = ((const float4*)b)[c4];
        float4 u  = v[j];
        float4 o;
        o.x = (u.x - mu) * rs * wv.x + bv.x;
        o.y = (u.y - mu) * rs * wv.y + bv.y;
        o.z = (u.z - mu) * rs * wv.z + bv.z;
        o.w = (u.w - mu) * rs * wv.w + bv.w;
        po[c4] = o;
        if (j == 0 && lane < 16) {
            int k = lane * 4;
            float q0 = __cosf(o.x + fqp[(k + 0) * 3]) * __cosf(fqp[(k + 0) * 3 + 1]);
            float q1 = __cosf(o.y + fqp[(k + 1) * 3]) * __cosf(fqp[(k + 1) * 3 + 1]);
            float q2 = __cosf(o.z + fqp[(k + 2) * 3]) * __cosf(fqp[(k + 2) * 3 + 1]);
            float q3 = __cosf(o.w + fqp[(k + 3) * 3]) * __cosf(fqp[(k + 3) * 3 + 1]);
            BPack h, l;
            h.b[0] = __float2bfloat16(q0); l.b[0] = __float2bfloat16(q0 - __bfloat162float(h.b[0]));
            h.b[1] = __float2bfloat16(q1); l.b[1] = __float2bfloat16(q1 - __bfloat162float(h.b[1]));
            h.b[2] = __float2bfloat16(q2); l.b[2] = __float2bfloat16(q2 - __bfloat162float(h.b[2]));
            h.b[3] = __float2bfloat16(q3); l.b[3] = __float2bfloat16(q3 - __bfloat162float(h.b[3]));
            *(uint2*)(qhi + (size_t)row * NQ + k) = h.u;
            *(uint2*)(qlo + (size_t)row * NQ + k) = l.u;
        }
    }
}

// ---------------- LN2 ----------------
__global__ __launch_bounds__(256) void ln2_kernel(const float* __restrict__ x1,
                                                  const float* __restrict__ ffn,
                                                  const float* __restrict__ w,
                                                  const float* __restrict__ b,
                                                  float* __restrict__ out) {
    int row  = blockIdx.x * 8 + (threadIdx.x >> 5);
    int lane = threadIdx.x & 31;
    const float4* px = (const float4*)(x1  + (size_t)row * E_DIM);
    const float4* pf = (const float4*)(ffn + (size_t)row * E_DIM);
    float4 v[8];
    float s = 0.f, ss = 0.f;
    #pragma unroll
    for (int j = 0; j < 8; ++j) {
        float4 a = px[lane + j * 32];
        float4 t = pf[lane + j * 32];
        float4 u = {a.x + t.x, a.y + t.y, a.z + t.z, a.w + t.w};
        v[j] = u;
        s  += u.x + u.y + u.z + u.w;
        ss += u.x * u.x + u.y * u.y + u.z * u.z + u.w * u.w;
    }
    #pragma unroll
    for (int o = 16; o; o >>= 1) {
        s  += __shfl_xor_sync(0xffffffffu, s, o);
        ss += __shfl_xor_sync(0xffffffffu, ss, o);
    }
    float mu  = s * (1.f / E_DIM);
    float var = ss * (1.f / E_DIM) - mu * mu;
    float rs  = rsqrtf(var + 1e-5f);

    float4* po = (float4*)(out + (size_t)row * E_DIM);
    #pragma unroll
    for (int j = 0; j < 8; ++j) {
        int c4 = lane + j * 32;
        float4 wv = ((const float4*)w)[c4];
        float4 bv = ((const float4*)b)[c4];
        float4 u  = v[j];
        float4 o;
        o.x = (u.x - mu) * rs * wv.x + bv.x;
        o.y = (u.y - mu) * rs * wv.y + bv.y;
        o.z = (u.z - mu) * rs * wv.z + bv.z;
        o.w = (u.w - mu) * rs * wv.w + bv.w;
        po[c4] = o;
    }
}

// ---------------- launcher ----------------
extern "C" void kernel_launch(void* const* d_in, const int* in_sizes, int n_in,
                              void* d_out, int out_size) {
    const float* x   = (const float*)d_in[0];
    const float* aqp = (const float*)d_in[1];
    const float* opw = (const float*)d_in[2];
    const float* opb = (const float*)d_in[3];
    const float* fqp = (const float*)d_in[4];
    const float* flw = (const float*)d_in[5];
    const float* flb = (const float*)d_in[6];
    const float* n1w = (const float*)d_in[7];
    const float* n1b = (const float*)d_in[8];
    const float* n2w = (const float*)d_in[9];
    const float* n2b = (const float*)d_in[10];
    float* out = (float*)d_out;

    float *attn, *x1;
    __nv_bfloat16 *zhi, *zlo, *whi, *wlo, *w2hi, *w2lo, *qhi, *qlo;
    cudaGetSymbolAddress((void**)&attn, g_attn);
    cudaGetSymbolAddress((void**)&x1,   g_x1);
    cudaGetSymbolAddress((void**)&zhi,  g_zhi);
    cudaGetSymbolAddress((void**)&zlo,  g_zlo);
    cudaGetSymbolAddress((void**)&whi,  g_whi);
    cudaGetSymbolAddress((void**)&wlo,  g_wlo);
    cudaGetSymbolAddress((void**)&w2hi, g_w2hi);
    cudaGetSymbolAddress((void**)&w2lo, g_w2lo);
    cudaGetSymbolAddress((void**)&qhi,  g_qhi);
    cudaGetSymbolAddress((void**)&qlo,  g_qlo);

    cudaFuncSetAttribute(mma_gemm, cudaFuncAttributeMaxDynamicSharedMemorySize, SM_TOT);

    // 1) z -> (zhi, zlo)
    z_split_kernel<<<(M_TOK * E_DIM / 4) / 256, 256>>>(x, aqp, zhi, zlo);
    // 2) weight splits
    w_split_kernel<<<2048, 256>>>(opw, whi, wlo, E_DIM * E_DIM);
    w_split_kernel<<<256, 256>>>(flw, w2hi, w2lo, E_DIM * NQ);
    // 3) attn = z @ opw^T + opb   (bf16-split mma.sync)
    dim3 g1(E_DIM / BN, M_TOK / BM);
    mma_gemm<<<g1, 256, SM_TOT>>>(zhi, zlo, whi, wlo, opb, attn, E_DIM);
    // 4) x1 = LN1(x + attn); q -> (qhi, qlo)
    ln1_kernel<<<M_TOK / 8, 256>>>(x, attn, n1w, n1b, fqp, x1, qhi, qlo);
    // 5) ffn = q @ flw^T + flb   (K = 64)
    mma_gemm<<<g1, 256, SM_TOT>>>(qhi, qlo, w2hi, w2lo, flb, attn, NQ);
    // 6) out = LN2(x1 + ffn)
    ln2_kernel<<<M_TOK / 8, 256>>>(x1, attn, n2w, n2b, out);
}